// round 15
// baseline (speedup 1.0000x reference)
#include <cuda_runtime.h>
#include <cuda_bf16.h>
#include <cstdint>

#define NN 50000
#define NE 800000
#define F 128
#define NC 16
#define NBLK 196     // 196*256 = 50176 >= NN
#define NT_G1 ((NN + 127) / 128)   // 391 tiles
#define G1_CTAS 148

// ---------------- scratch (static device globals; no allocs) ----------------
__device__ float g_h1[(size_t)NN * F];
__device__ __nv_bfloat16 g_nbh[(size_t)NN * F];
__device__ float g_D [(size_t)NN * NC];
__device__ int   g_deg[NN];
__device__ int   g_cur[NN];
__device__ int   g_rowoff[NN + 1];
__device__ int   g_esrc[NE];
__device__ int   g_part[NBLK * 256];
__device__ int   g_bsum[NBLK];
__device__ int   g_is64;
__device__ __nv_bfloat16 g_wThi[2 * F * F];
__device__ __nv_bfloat16 g_wTlo[2 * F * F];
__device__ __nv_bfloat16 g_w2Thi[32 * F];
__device__ __nv_bfloat16 g_w2Tlo[32 * F];
__device__ __nv_bfloat16 g_h1hi[(size_t)NN * F];
__device__ __nv_bfloat16 g_h1lo[(size_t)NN * F];

// ---------------- helpers ----------------
__device__ __forceinline__ uint32_t smem_u32(const void* p) {
    uint32_t a;
    asm("{ .reg .u64 t; cvta.to.shared.u64 t, %1; cvt.u32.u64 %0, t; }"
        : "=r"(a) : "l"(p));
    return a;
}
__device__ __forceinline__ void ldm_x4(uint32_t* r, uint32_t addr) {
    asm volatile("ldmatrix.sync.aligned.m8n8.x4.shared.b16 {%0,%1,%2,%3}, [%4];"
                 : "=r"(r[0]), "=r"(r[1]), "=r"(r[2]), "=r"(r[3]) : "r"(addr));
}
__device__ __forceinline__ void ldm_x2(uint32_t* r, uint32_t addr) {
    asm volatile("ldmatrix.sync.aligned.m8n8.x2.shared.b16 {%0,%1}, [%2];"
                 : "=r"(r[0]), "=r"(r[1]) : "r"(addr));
}
__device__ __forceinline__ void mma16816(float* d, const uint32_t* a, const uint32_t* b) {
    asm volatile("mma.sync.aligned.m16n8k16.row.col.f32.bf16.bf16.f32 "
                 "{%0,%1,%2,%3}, {%4,%5,%6,%7}, {%8,%9}, {%0,%1,%2,%3};"
                 : "+f"(d[0]), "+f"(d[1]), "+f"(d[2]), "+f"(d[3])
                 : "r"(a[0]), "r"(a[1]), "r"(a[2]), "r"(a[3]), "r"(b[0]), "r"(b[1]));
}
__device__ __forceinline__ uint32_t pack_bf2(float a, float b) {
    __nv_bfloat162 t(__float2bfloat16(a), __float2bfloat16(b));
    return *reinterpret_cast<uint32_t*>(&t);
}

// -------- zero + dtype detect (CSR stream) ----------------------------------
__global__ void zero_k(const int* __restrict__ dst32) {
    int i = blockIdx.x * blockDim.x + threadIdx.x;
    if (i < NN) { g_deg[i] = 0; g_cur[i] = 0; }
    if (i == 0) {
        int all_zero = 1;
        for (int j = 0; j < 256; j++)
            if (dst32[2 * j + 1] != 0) { all_zero = 0; break; }
        g_is64 = all_zero;
    }
}

// -------- weight conversions (main stream, feeds gemm1/gemm2) ---------------
__global__ void prep_w(const float* __restrict__ Ws1, const float* __restrict__ Wn1,
                       const float* __restrict__ Ws2, const float* __restrict__ Wn2) {
    int i = blockIdx.x * blockDim.x + threadIdx.x;
    if (i < 2 * F * F) {
        int mat = i >> 14, n = (i >> 7) & 127, k = i & 127;
        float w = (mat == 0) ? Ws1[k * F + n] : Wn1[k * F + n];
        __nv_bfloat16 h = __float2bfloat16(w);
        g_wThi[i] = h;
        g_wTlo[i] = __float2bfloat16(w - __bfloat162float(h));
    } else if (i < 2 * F * F + 32 * F) {
        int i2 = i - 2 * F * F;
        int n = i2 >> 7, k = i2 & 127;
        float w = (n < 16) ? Ws2[k * 16 + n] : Wn2[k * 16 + (n - 16)];
        __nv_bfloat16 h = __float2bfloat16(w);
        g_w2Thi[i2] = h;
        g_w2Tlo[i2] = __float2bfloat16(w - __bfloat162float(h));
    }
}
__device__ __forceinline__ int load_idx(const void* p, int i) {
    if (g_is64) return (int)((const long long*)p)[i];
    return ((const int*)p)[i];
}

// ---------------- CSR build ----------------
__global__ void count_k(const void* __restrict__ dst) {
    int i = blockIdx.x * blockDim.x + threadIdx.x;
    if (i < NE) {
        int d = load_idx(dst, i);
        if (d >= 0 && d < NN) atomicAdd(&g_deg[d], 1);
    }
}
__global__ void scanA_k() {
    __shared__ int sh[256];
    int t = threadIdx.x, i = blockIdx.x * 256 + t;
    int v = (i < NN) ? g_deg[i] : 0;
    sh[t] = v;
    __syncthreads();
#pragma unroll
    for (int off = 1; off < 256; off <<= 1) {
        int u = (t >= off) ? sh[t - off] : 0;
        __syncthreads();
        sh[t] += u;
        __syncthreads();
    }
    g_part[i] = sh[t];
    if (t == 255) g_bsum[blockIdx.x] = sh[255];
}
__global__ void scanC_k() {
    __shared__ int red[256];
    int t = threadIdx.x, b = blockIdx.x;
    red[t] = (t < b) ? g_bsum[t] : 0;
    __syncthreads();
#pragma unroll
    for (int off = 128; off >= 1; off >>= 1) {
        if (t < off) red[t] += red[t + off];
        __syncthreads();
    }
    int prefix = red[0];
    int i = b * 256 + t;
    if (i < NN) {
        g_rowoff[i + 1] = g_part[i] + prefix;
        if (i == 0) g_rowoff[0] = 0;
    }
}
__global__ void fill_k(const void* __restrict__ src, const void* __restrict__ dst) {
    int i = blockIdx.x * blockDim.x + threadIdx.x;
    if (i < NE) {
        int d = load_idx(dst, i);
        int s = load_idx(src, i);
        if (d < 0 || d >= NN || s < 0 || s >= NN) return;
        int pos = atomicAdd(&g_cur[d], 1);
        int off = g_rowoff[d] + pos;
        if (off < NE) g_esrc[off] = s;
    }
}

// ------- layer-1 GEMM: persistent, B staged once, A prefetched --------------
#define RS 136
#define TILE_B (128 * RS * 2)
#define OFF_AHI 0
#define OFF_ALO (TILE_B)
#define OFF_BHI (2 * TILE_B)
#define OFF_BLO (4 * TILE_B)
#define SMEM_G1 (6 * TILE_B)

__global__ void __launch_bounds__(512, 1)
gemm1_mma(const float* __restrict__ X, const float* __restrict__ b1) {
    extern __shared__ char smem[];
    uint32_t sb = smem_u32(smem);
    int tid = threadIdx.x, wid = tid >> 5, lane = tid & 31;

    // stage B once: 256 rows (mat0 then mat1) x 16 chunks
    for (int i = tid; i < 256 * 16; i += 512) {
        int r = i >> 4, cc = i & 15;
        uint32_t so = (uint32_t)r * (RS * 2) + cc * 16;
        *reinterpret_cast<uint4*>(smem + OFF_BHI + so) =
            reinterpret_cast<const uint4*>(g_wThi + (size_t)r * F)[cc];
        *reinterpret_cast<uint4*>(smem + OFF_BLO + so) =
            reinterpret_cast<const uint4*>(g_wTlo + (size_t)r * F)[cc];
    }

    float4 pf[8];
    int tile = blockIdx.x;
    {
#pragma unroll
        for (int j = 0; j < 4; j++) {
            int slot = tid + j * 512;
            int r = slot >> 4, cc = slot & 15;
            int gr = tile * 128 + r;
            float4 a = make_float4(0.f, 0.f, 0.f, 0.f), b = a;
            if (tile < NT_G1 && gr < NN) {
                const float4* xp = reinterpret_cast<const float4*>(X + (size_t)gr * F + cc * 8);
                a = xp[0]; b = xp[1];
            }
            pf[2 * j] = a; pf[2 * j + 1] = b;
        }
    }

    int wm = (wid & 3) * 32;
    int wnBase = (wid >> 2) * 64;
    uint32_t a_row = wm + (lane & 15);
    uint32_t a_coff = (lane >> 4) * 16;
    uint32_t b_rowL = (lane & 7);
    uint32_t b_coff = ((lane >> 3) & 1) * 16;

    for (; tile < NT_G1; tile += G1_CTAS) {
#pragma unroll
        for (int j = 0; j < 4; j++) {
            int slot = tid + j * 512;
            int r = slot >> 4, cc = slot & 15;
            uint32_t so = (uint32_t)r * (RS * 2) + cc * 16;
            float v[8];
            v[0] = pf[2 * j].x; v[1] = pf[2 * j].y; v[2] = pf[2 * j].z; v[3] = pf[2 * j].w;
            v[4] = pf[2 * j + 1].x; v[5] = pf[2 * j + 1].y;
            v[6] = pf[2 * j + 1].z; v[7] = pf[2 * j + 1].w;
            float hf[8], lf[8];
#pragma unroll
            for (int q = 0; q < 8; q++) {
                __nv_bfloat16 h = __float2bfloat16(v[q]);
                hf[q] = __bfloat162float(h);
                lf[q] = v[q] - hf[q];
            }
            *reinterpret_cast<uint4*>(smem + OFF_AHI + so) =
                make_uint4(pack_bf2(hf[0], hf[1]), pack_bf2(hf[2], hf[3]),
                           pack_bf2(hf[4], hf[5]), pack_bf2(hf[6], hf[7]));
            *reinterpret_cast<uint4*>(smem + OFF_ALO + so) =
                make_uint4(pack_bf2(lf[0], lf[1]), pack_bf2(lf[2], lf[3]),
                           pack_bf2(lf[4], lf[5]), pack_bf2(lf[6], lf[7]));
        }
        __syncthreads();

        int ntile = tile + G1_CTAS;
        if (ntile < NT_G1) {
#pragma unroll
            for (int j = 0; j < 4; j++) {
                int slot = tid + j * 512;
                int r = slot >> 4, cc = slot & 15;
                int gr = ntile * 128 + r;
                float4 a = make_float4(0.f, 0.f, 0.f, 0.f), b = a;
                if (gr < NN) {
                    const float4* xp = reinterpret_cast<const float4*>(X + (size_t)gr * F + cc * 8);
                    a = xp[0]; b = xp[1];
                }
                pf[2 * j] = a; pf[2 * j + 1] = b;
            }
        }

        int rowBase = tile * 128;
#pragma unroll
        for (int half = 0; half < 2; half++) {
            float acc[2][4][4];
#pragma unroll
            for (int mt = 0; mt < 2; mt++)
#pragma unroll
                for (int nt = 0; nt < 4; nt++)
#pragma unroll
                    for (int e = 0; e < 4; e++) acc[mt][nt][e] = 0.f;

#pragma unroll
            for (int ks = 0; ks < 8; ks++) {
                uint32_t kb = ks * 32;
                uint32_t ahi[2][4], alo[2][4], bhi[4][2], blo[4][2];
#pragma unroll
                for (int mt = 0; mt < 2; mt++) {
                    uint32_t ro = (a_row + mt * 16) * (RS * 2) + kb + a_coff;
                    ldm_x4(ahi[mt], sb + OFF_AHI + ro);
                    ldm_x4(alo[mt], sb + OFF_ALO + ro);
                }
#pragma unroll
                for (int nt = 0; nt < 4; nt++) {
                    uint32_t br = wnBase + half * 32 + nt * 8 + b_rowL;
                    uint32_t ro = br * (RS * 2) + kb + b_coff;
                    ldm_x2(bhi[nt], sb + OFF_BHI + ro);
                    ldm_x2(blo[nt], sb + OFF_BLO + ro);
                }
#pragma unroll
                for (int mt = 0; mt < 2; mt++)
#pragma unroll
                    for (int nt = 0; nt < 4; nt++) {
                        mma16816(acc[mt][nt], ahi[mt], bhi[nt]);
                        mma16816(acc[mt][nt], alo[mt], bhi[nt]);
                        mma16816(acc[mt][nt], ahi[mt], blo[nt]);
                    }
            }

#pragma unroll
            for (int mt = 0; mt < 2; mt++) {
                int r0 = rowBase + wm + mt * 16 + (lane >> 2);
                int r1 = r0 + 8;
#pragma unroll
                for (int nt = 0; nt < 4; nt++) {
                    int c = wnBase + half * 32 + nt * 8 + (lane & 3) * 2;
                    if (c < 128) {
                        float bs0 = __ldg(&b1[c]), bs1 = __ldg(&b1[c + 1]);
                        if (r0 < NN)
                            *reinterpret_cast<float2*>(g_h1 + (size_t)r0 * F + c) =
                                make_float2(acc[mt][nt][0] + bs0, acc[mt][nt][1] + bs1);
                        if (r1 < NN)
                            *reinterpret_cast<float2*>(g_h1 + (size_t)r1 * F + c) =
                                make_float2(acc[mt][nt][2] + bs0, acc[mt][nt][3] + bs1);
                    } else {
                        int cc = c - 128;
                        if (r0 < NN)
                            *reinterpret_cast<uint32_t*>(g_nbh + (size_t)r0 * F + cc) =
                                pack_bf2(acc[mt][nt][0], acc[mt][nt][1]);
                        if (r1 < NN)
                            *reinterpret_cast<uint32_t*>(g_nbh + (size_t)r1 * F + cc) =
                                pack_bf2(acc[mt][nt][2], acc[mt][nt][3]);
                    }
                }
            }
        }
        __syncthreads();
    }
}

// ------- layer-1 aggregate: 1 node/warp, half-warps split even/odd edges ----
__global__ void agg1_k() {
    int node = (blockIdx.x * blockDim.x + threadIdx.x) >> 5;
    if (node >= NN) return;
    int lane = threadIdx.x & 31;
    int sl = lane & 15, side = lane >> 4;
    int beg = g_rowoff[node], end = g_rowoff[node + 1];
    float s[8] = {0.f, 0.f, 0.f, 0.f, 0.f, 0.f, 0.f, 0.f};
    int e = beg + side;
    // 4 edges per lane-side per iteration = 8 edges per warp
    for (; e + 6 < end; e += 8) {
        int idx[4];
        uint4 u[4];
#pragma unroll
        for (int j = 0; j < 4; j++) idx[j] = g_esrc[e + 2 * j];
#pragma unroll
        for (int j = 0; j < 4; j++)
            u[j] = reinterpret_cast<const uint4*>(g_nbh + (size_t)idx[j] * F)[sl];
#pragma unroll
        for (int j = 0; j < 4; j++) {
            float2 a0 = __bfloat1622float2(*reinterpret_cast<__nv_bfloat162*>(&u[j].x));
            float2 a1 = __bfloat1622float2(*reinterpret_cast<__nv_bfloat162*>(&u[j].y));
            float2 a2 = __bfloat1622float2(*reinterpret_cast<__nv_bfloat162*>(&u[j].z));
            float2 a3 = __bfloat1622float2(*reinterpret_cast<__nv_bfloat162*>(&u[j].w));
            s[0] += a0.x; s[1] += a0.y; s[2] += a1.x; s[3] += a1.y;
            s[4] += a2.x; s[5] += a2.y; s[6] += a3.x; s[7] += a3.y;
        }
    }
    for (; e < end; e += 2) {
        uint4 u = reinterpret_cast<const uint4*>(g_nbh + (size_t)g_esrc[e] * F)[sl];
        float2 a0 = __bfloat1622float2(*reinterpret_cast<__nv_bfloat162*>(&u.x));
        float2 a1 = __bfloat1622float2(*reinterpret_cast<__nv_bfloat162*>(&u.y));
        float2 a2 = __bfloat1622float2(*reinterpret_cast<__nv_bfloat162*>(&u.z));
        float2 a3 = __bfloat1622float2(*reinterpret_cast<__nv_bfloat162*>(&u.w));
        s[0] += a0.x; s[1] += a0.y; s[2] += a1.x; s[3] += a1.y;
        s[4] += a2.x; s[5] += a2.y; s[6] += a3.x; s[7] += a3.y;
    }
    // combine even/odd halves (lane and lane^16 hold same feature chunk)
#pragma unroll
    for (int j = 0; j < 8; j++)
        s[j] += __shfl_xor_sync(0xffffffffu, s[j], 16);

    if (side == 0) {
        float inv = 1.0f / fmaxf((float)(end - beg), 1.0f);
        const float4* hp = reinterpret_cast<const float4*>(g_h1 + (size_t)node * F) + sl * 2;
        float4 h0 = hp[0], h1v = hp[1];
        float r[8];
        r[0] = fmaxf(h0.x + s[0] * inv, 0.f);
        r[1] = fmaxf(h0.y + s[1] * inv, 0.f);
        r[2] = fmaxf(h0.z + s[2] * inv, 0.f);
        r[3] = fmaxf(h0.w + s[3] * inv, 0.f);
        r[4] = fmaxf(h1v.x + s[4] * inv, 0.f);
        r[5] = fmaxf(h1v.y + s[5] * inv, 0.f);
        r[6] = fmaxf(h1v.z + s[6] * inv, 0.f);
        r[7] = fmaxf(h1v.w + s[7] * inv, 0.f);
        float hi[8], lo[8];
#pragma unroll
        for (int j = 0; j < 8; j++) {
            hi[j] = __bfloat162float(__float2bfloat16(r[j]));
            lo[j] = r[j] - hi[j];
        }
        uint4 uh = make_uint4(pack_bf2(hi[0], hi[1]), pack_bf2(hi[2], hi[3]),
                              pack_bf2(hi[4], hi[5]), pack_bf2(hi[6], hi[7]));
        uint4 ul = make_uint4(pack_bf2(lo[0], lo[1]), pack_bf2(lo[2], lo[3]),
                              pack_bf2(lo[4], lo[5]), pack_bf2(lo[6], lo[7]));
        reinterpret_cast<uint4*>(g_h1hi + (size_t)node * F)[sl] = uh;
        reinterpret_cast<uint4*>(g_h1lo + (size_t)node * F)[sl] = ul;
    }
}

// ---------------- layer-2 GEMM (mma.sync, N=32 = [self|neigh]) --------------
#define B2_B (32 * RS * 2)
#define OFF2_AHI 0
#define OFF2_ALO (TILE_B)
#define OFF2_BHI (2 * TILE_B)
#define OFF2_BLO (2 * TILE_B + B2_B)
#define SMEM_G2 (2 * TILE_B + 2 * B2_B)

__global__ void __launch_bounds__(256, 1)
gemm2_mma(const float* __restrict__ b2, float* __restrict__ out) {
    extern __shared__ char smem[];
    uint32_t sb = smem_u32(smem);
    int tid = threadIdx.x, wid = tid >> 5, lane = tid & 31;
    int rowBase = blockIdx.x * 128;

    for (int i = tid; i < 128 * 16; i += 256) {
        int r = i >> 4, cc = i & 15;
        uint32_t so = (uint32_t)r * (RS * 2) + cc * 16;
        int gr = rowBase + r;
        uint4 vh = make_uint4(0, 0, 0, 0), vl = make_uint4(0, 0, 0, 0);
        if (gr < NN) {
            vh = reinterpret_cast<const uint4*>(g_h1hi + (size_t)gr * F)[cc];
            vl = reinterpret_cast<const uint4*>(g_h1lo + (size_t)gr * F)[cc];
        }
        *reinterpret_cast<uint4*>(smem + OFF2_AHI + so) = vh;
        *reinterpret_cast<uint4*>(smem + OFF2_ALO + so) = vl;
    }
    for (int i = tid; i < 32 * 16; i += 256) {
        int r = i >> 4, cc = i & 15;
        uint32_t so = (uint32_t)r * (RS * 2) + cc * 16;
        *reinterpret_cast<uint4*>(smem + OFF2_BHI + so) =
            reinterpret_cast<const uint4*>(g_w2Thi + (size_t)r * F)[cc];
        *reinterpret_cast<uint4*>(smem + OFF2_BLO + so) =
            reinterpret_cast<const uint4*>(g_w2Tlo + (size_t)r * F)[cc];
    }
    __syncthreads();

    int wm = (wid & 3) * 32, wn = (wid >> 2) * 16;
    float acc[2][2][4];
#pragma unroll
    for (int mt = 0; mt < 2; mt++)
#pragma unroll
        for (int nt = 0; nt < 2; nt++)
#pragma unroll
            for (int e = 0; e < 4; e++) acc[mt][nt][e] = 0.f;

    uint32_t a_row = wm + (lane & 15);
    uint32_t a_coff = (lane >> 4) * 16;
    uint32_t b_row = wn + (lane & 7);
    uint32_t b_coff = ((lane >> 3) & 1) * 16;

#pragma unroll
    for (int ks = 0; ks < 8; ks++) {
        uint32_t kb = ks * 32;
        uint32_t ahi[2][4], alo[2][4], bhi[2][2], blo[2][2];
#pragma unroll
        for (int mt = 0; mt < 2; mt++) {
            uint32_t ro = (a_row + mt * 16) * (RS * 2) + kb + a_coff;
            ldm_x4(ahi[mt], sb + OFF2_AHI + ro);
            ldm_x4(alo[mt], sb + OFF2_ALO + ro);
        }
#pragma unroll
        for (int nt = 0; nt < 2; nt++) {
            uint32_t ro = (b_row + nt * 8) * (RS * 2) + kb + b_coff;
            ldm_x2(bhi[nt], sb + OFF2_BHI + ro);
            ldm_x2(blo[nt], sb + OFF2_BLO + ro);
        }
#pragma unroll
        for (int mt = 0; mt < 2; mt++)
#pragma unroll
            for (int nt = 0; nt < 2; nt++) {
                mma16816(acc[mt][nt], ahi[mt], bhi[nt]);
                mma16816(acc[mt][nt], alo[mt], bhi[nt]);
                mma16816(acc[mt][nt], ahi[mt], blo[nt]);
            }
    }

#pragma unroll
    for (int mt = 0; mt < 2; mt++) {
        int r0 = rowBase + wm + mt * 16 + (lane >> 2);
        int r1 = r0 + 8;
#pragma unroll
        for (int nt = 0; nt < 2; nt++) {
            int cg = wn + nt * 8 + (lane & 3) * 2;
            if (cg < 16) {
                float bs0 = __ldg(&b2[cg]), bs1 = __ldg(&b2[cg + 1]);
                if (r0 < NN)
                    *reinterpret_cast<float2*>(out + (size_t)r0 * NC + cg) =
                        make_float2(acc[mt][nt][0] + bs0, acc[mt][nt][1] + bs1);
                if (r1 < NN)
                    *reinterpret_cast<float2*>(out + (size_t)r1 * NC + cg) =
                        make_float2(acc[mt][nt][2] + bs0, acc[mt][nt][3] + bs1);
            } else {
                int cd = cg - 16;
                if (r0 < NN)
                    *reinterpret_cast<float2*>(g_D + (size_t)r0 * NC + cd) =
                        make_float2(acc[mt][nt][0], acc[mt][nt][1]);
                if (r1 < NN)
                    *reinterpret_cast<float2*>(g_D + (size_t)r1 * NC + cd) =
                        make_float2(acc[mt][nt][2], acc[mt][nt][3]);
            }
        }
    }
}

// ---------------- layer-2 aggregate + add ----------------
__global__ void agg2_k(float* __restrict__ out) {
    int idx = blockIdx.x * blockDim.x + threadIdx.x;
    int node = idx >> 4;
    if (node >= NN) return;
    int dim = idx & 15;
    int beg = g_rowoff[node], end = g_rowoff[node + 1];
    float s = 0.f;
    int e = beg;
    for (; e + 8 <= end; e += 8) {
        int id[8];
        float v[8];
#pragma unroll
        for (int j = 0; j < 8; j++) id[j] = g_esrc[e + j];
#pragma unroll
        for (int j = 0; j < 8; j++) v[j] = g_D[(size_t)id[j] * NC + dim];
        s += ((v[0] + v[1]) + (v[2] + v[3])) + ((v[4] + v[5]) + (v[6] + v[7]));
    }
    for (; e + 4 <= end; e += 4) {
        int i0 = g_esrc[e], i1 = g_esrc[e + 1], i2 = g_esrc[e + 2], i3 = g_esrc[e + 3];
        float v0 = g_D[(size_t)i0 * NC + dim];
        float v1 = g_D[(size_t)i1 * NC + dim];
        float v2 = g_D[(size_t)i2 * NC + dim];
        float v3 = g_D[(size_t)i3 * NC + dim];
        s += (v0 + v1) + (v2 + v3);
    }
    for (; e < end; e++)
        s += g_D[(size_t)g_esrc[e] * NC + dim];
    float inv = 1.0f / fmaxf((float)(end - beg), 1.0f);
    out[(size_t)node * NC + dim] += s * inv;
}

// ---------------- launch ----------------
extern "C" void kernel_launch(void* const* d_in, const int* in_sizes, int n_in,
                              void* d_out, int out_size)
{
    const float* in_feat = (const float*)d_in[0];
    const void*  src     = d_in[1];
    const void*  dst     = d_in[2];
    const float* Wself1  = (const float*)d_in[3];
    const float* Wneigh1 = (const float*)d_in[4];
    const float* b1      = (const float*)d_in[5];
    const float* Wself2  = (const float*)d_in[6];
    const float* Wneigh2 = (const float*)d_in[7];
    const float* b2      = (const float*)d_in[8];
    float* out = (float*)d_out;

    static cudaStream_t s2 = nullptr;
    static cudaEvent_t evFork = nullptr, evJoin = nullptr;
    if (!s2) {
        cudaFuncSetAttribute(gemm1_mma, cudaFuncAttributeMaxDynamicSharedMemorySize, SMEM_G1);
        cudaFuncSetAttribute(gemm2_mma, cudaFuncAttributeMaxDynamicSharedMemorySize, SMEM_G2);
        cudaStreamCreateWithFlags(&s2, cudaStreamNonBlocking);
        cudaEventCreateWithFlags(&evFork, cudaEventDisableTiming);
        cudaEventCreateWithFlags(&evJoin, cudaEventDisableTiming);
    }

    // fork at entry: CSR chain (incl. zero+detect) on s2
    cudaEventRecord(evFork, 0);
    cudaStreamWaitEvent(s2, evFork, 0);
    zero_k <<<NBLK, 256, 0, s2>>>((const int*)dst);
    count_k<<<(NE + 255) / 256, 256, 0, s2>>>(dst);
    scanA_k<<<NBLK, 256, 0, s2>>>();
    scanC_k<<<NBLK, 256, 0, s2>>>();
    fill_k <<<(NE + 255) / 256, 256, 0, s2>>>(src, dst);
    cudaEventRecord(evJoin, s2);

    // main: weights-only prep -> persistent gemm1
    prep_w<<<(2 * F * F + 32 * F + 255) / 256, 256>>>(Wself1, Wneigh1, Wself2, Wneigh2);
    gemm1_mma<<<G1_CTAS, 512, SMEM_G1>>>(in_feat, b1);

    // join: agg1 needs both fill_k (s2) and gemm1 (main)
    cudaStreamWaitEvent(0, evJoin, 0);

    agg1_k<<<(NN * 32 + 255) / 256, 256>>>();
    gemm2_mma<<<(NN + 127) / 128, 256, SMEM_G2>>>(b2, out);
    agg2_k<<<(NN * 16 + 255) / 256, 256>>>(out);
}

// round 16
// speedup vs baseline: 1.0923x; 1.0923x over previous
#include <cuda_runtime.h>
#include <cuda_bf16.h>
#include <cstdint>

#define NN 50000
#define NE 800000
#define F 128
#define NC 16
#define NBLK 196     // 196*256 = 50176 >= NN
#define NT_G1 ((NN + 127) / 128)   // 391 tiles
#define G1_CTAS 148

// ---------------- scratch (static device globals; no allocs) ----------------
__device__ float g_h1[(size_t)NN * F];
__device__ __nv_bfloat16 g_nbh[(size_t)NN * F];
__device__ float g_D [(size_t)NN * NC];
__device__ int   g_deg[NN];
__device__ int   g_cur[NN];
__device__ int   g_rowoff[NN + 1];
__device__ int   g_esrc[NE];
__device__ int   g_part[NBLK * 256];
__device__ int   g_bsum[NBLK];
__device__ int   g_is64;
__device__ __nv_bfloat16 g_wThi[2 * F * F];
__device__ __nv_bfloat16 g_wTlo[2 * F * F];
__device__ __nv_bfloat16 g_w2Thi[32 * F];
__device__ __nv_bfloat16 g_w2Tlo[32 * F];
__device__ __nv_bfloat16 g_h1hi[(size_t)NN * F];
__device__ __nv_bfloat16 g_h1lo[(size_t)NN * F];

// ---------------- helpers ----------------
__device__ __forceinline__ uint32_t smem_u32(const void* p) {
    uint32_t a;
    asm("{ .reg .u64 t; cvta.to.shared.u64 t, %1; cvt.u32.u64 %0, t; }"
        : "=r"(a) : "l"(p));
    return a;
}
__device__ __forceinline__ void ldm_x4(uint32_t* r, uint32_t addr) {
    asm volatile("ldmatrix.sync.aligned.m8n8.x4.shared.b16 {%0,%1,%2,%3}, [%4];"
                 : "=r"(r[0]), "=r"(r[1]), "=r"(r[2]), "=r"(r[3]) : "r"(addr));
}
__device__ __forceinline__ void ldm_x2(uint32_t* r, uint32_t addr) {
    asm volatile("ldmatrix.sync.aligned.m8n8.x2.shared.b16 {%0,%1}, [%2];"
                 : "=r"(r[0]), "=r"(r[1]) : "r"(addr));
}
__device__ __forceinline__ void mma16816(float* d, const uint32_t* a, const uint32_t* b) {
    asm volatile("mma.sync.aligned.m16n8k16.row.col.f32.bf16.bf16.f32 "
                 "{%0,%1,%2,%3}, {%4,%5,%6,%7}, {%8,%9}, {%0,%1,%2,%3};"
                 : "+f"(d[0]), "+f"(d[1]), "+f"(d[2]), "+f"(d[3])
                 : "r"(a[0]), "r"(a[1]), "r"(a[2]), "r"(a[3]), "r"(b[0]), "r"(b[1]));
}
__device__ __forceinline__ uint32_t pack_bf2(float a, float b) {
    __nv_bfloat162 t(__float2bfloat16(a), __float2bfloat16(b));
    return *reinterpret_cast<uint32_t*>(&t);
}

// -------- prep: zero deg/cur + dtype detect + weight conversions ------------
__global__ void prep_k(const int* __restrict__ dst32,
                       const float* __restrict__ Ws1, const float* __restrict__ Wn1,
                       const float* __restrict__ Ws2, const float* __restrict__ Wn2) {
    int i = blockIdx.x * blockDim.x + threadIdx.x;
    if (i < NN) { g_deg[i] = 0; g_cur[i] = 0; }
    if (i == 0) {
        int all_zero = 1;
        for (int j = 0; j < 256; j++)
            if (dst32[2 * j + 1] != 0) { all_zero = 0; break; }
        g_is64 = all_zero;
    }
    if (i < 2 * F * F) {
        int mat = i >> 14, n = (i >> 7) & 127, k = i & 127;
        float w = (mat == 0) ? Ws1[k * F + n] : Wn1[k * F + n];
        __nv_bfloat16 h = __float2bfloat16(w);
        g_wThi[i] = h;
        g_wTlo[i] = __float2bfloat16(w - __bfloat162float(h));
    } else if (i < 2 * F * F + 32 * F) {
        int i2 = i - 2 * F * F;
        int n = i2 >> 7, k = i2 & 127;
        float w = (n < 16) ? Ws2[k * 16 + n] : Wn2[k * 16 + (n - 16)];
        __nv_bfloat16 h = __float2bfloat16(w);
        g_w2Thi[i2] = h;
        g_w2Tlo[i2] = __float2bfloat16(w - __bfloat162float(h));
    }
}
__device__ __forceinline__ int load_idx(const void* p, int i) {
    if (g_is64) return (int)((const long long*)p)[i];
    return ((const int*)p)[i];
}

// ---------------- CSR build ----------------
__global__ void count_k(const void* __restrict__ dst) {
    int i = blockIdx.x * blockDim.x + threadIdx.x;
    if (i < NE) {
        int d = load_idx(dst, i);
        if (d >= 0 && d < NN) atomicAdd(&g_deg[d], 1);
    }
}
__global__ void scanA_k() {
    __shared__ int sh[256];
    int t = threadIdx.x, i = blockIdx.x * 256 + t;
    int v = (i < NN) ? g_deg[i] : 0;
    sh[t] = v;
    __syncthreads();
#pragma unroll
    for (int off = 1; off < 256; off <<= 1) {
        int u = (t >= off) ? sh[t - off] : 0;
        __syncthreads();
        sh[t] += u;
        __syncthreads();
    }
    g_part[i] = sh[t];
    if (t == 255) g_bsum[blockIdx.x] = sh[255];
}
__global__ void scanC_k() {
    __shared__ int red[256];
    int t = threadIdx.x, b = blockIdx.x;
    red[t] = (t < b) ? g_bsum[t] : 0;
    __syncthreads();
#pragma unroll
    for (int off = 128; off >= 1; off >>= 1) {
        if (t < off) red[t] += red[t + off];
        __syncthreads();
    }
    int prefix = red[0];
    int i = b * 256 + t;
    if (i < NN) {
        g_rowoff[i + 1] = g_part[i] + prefix;
        if (i == 0) g_rowoff[0] = 0;
    }
}
__global__ void fill_k(const void* __restrict__ src, const void* __restrict__ dst) {
    int i = blockIdx.x * blockDim.x + threadIdx.x;
    if (i < NE) {
        int d = load_idx(dst, i);
        int s = load_idx(src, i);
        if (d < 0 || d >= NN || s < 0 || s >= NN) return;
        int pos = atomicAdd(&g_cur[d], 1);
        int off = g_rowoff[d] + pos;
        if (off < NE) g_esrc[off] = s;
    }
}

// ------- layer-1 GEMM: persistent, B staged once, A prefetched --------------
#define RS 136
#define TILE_B (128 * RS * 2)
#define OFF_AHI 0
#define OFF_ALO (TILE_B)
#define OFF_BHI (2 * TILE_B)
#define OFF_BLO (4 * TILE_B)
#define SMEM_G1 (6 * TILE_B)

__global__ void __launch_bounds__(512, 1)
gemm1_mma(const float* __restrict__ X, const float* __restrict__ b1) {
    extern __shared__ char smem[];
    uint32_t sb = smem_u32(smem);
    int tid = threadIdx.x, wid = tid >> 5, lane = tid & 31;

    // stage B once: 256 rows (mat0 then mat1) x 16 chunks
    for (int i = tid; i < 256 * 16; i += 512) {
        int r = i >> 4, cc = i & 15;
        uint32_t so = (uint32_t)r * (RS * 2) + cc * 16;
        *reinterpret_cast<uint4*>(smem + OFF_BHI + so) =
            reinterpret_cast<const uint4*>(g_wThi + (size_t)r * F)[cc];
        *reinterpret_cast<uint4*>(smem + OFF_BLO + so) =
            reinterpret_cast<const uint4*>(g_wTlo + (size_t)r * F)[cc];
    }

    float4 pf[8];
    int tile = blockIdx.x;
    {
#pragma unroll
        for (int j = 0; j < 4; j++) {
            int slot = tid + j * 512;
            int r = slot >> 4, cc = slot & 15;
            int gr = tile * 128 + r;
            float4 a = make_float4(0.f, 0.f, 0.f, 0.f), b = a;
            if (tile < NT_G1 && gr < NN) {
                const float4* xp = reinterpret_cast<const float4*>(X + (size_t)gr * F + cc * 8);
                a = xp[0]; b = xp[1];
            }
            pf[2 * j] = a; pf[2 * j + 1] = b;
        }
    }

    int wm = (wid & 3) * 32;
    int wnBase = (wid >> 2) * 64;
    uint32_t a_row = wm + (lane & 15);
    uint32_t a_coff = (lane >> 4) * 16;
    uint32_t b_rowL = (lane & 7);
    uint32_t b_coff = ((lane >> 3) & 1) * 16;

    for (; tile < NT_G1; tile += G1_CTAS) {
#pragma unroll
        for (int j = 0; j < 4; j++) {
            int slot = tid + j * 512;
            int r = slot >> 4, cc = slot & 15;
            uint32_t so = (uint32_t)r * (RS * 2) + cc * 16;
            float v[8];
            v[0] = pf[2 * j].x; v[1] = pf[2 * j].y; v[2] = pf[2 * j].z; v[3] = pf[2 * j].w;
            v[4] = pf[2 * j + 1].x; v[5] = pf[2 * j + 1].y;
            v[6] = pf[2 * j + 1].z; v[7] = pf[2 * j + 1].w;
            float hf[8], lf[8];
#pragma unroll
            for (int q = 0; q < 8; q++) {
                __nv_bfloat16 h = __float2bfloat16(v[q]);
                hf[q] = __bfloat162float(h);
                lf[q] = v[q] - hf[q];
            }
            *reinterpret_cast<uint4*>(smem + OFF_AHI + so) =
                make_uint4(pack_bf2(hf[0], hf[1]), pack_bf2(hf[2], hf[3]),
                           pack_bf2(hf[4], hf[5]), pack_bf2(hf[6], hf[7]));
            *reinterpret_cast<uint4*>(smem + OFF_ALO + so) =
                make_uint4(pack_bf2(lf[0], lf[1]), pack_bf2(lf[2], lf[3]),
                           pack_bf2(lf[4], lf[5]), pack_bf2(lf[6], lf[7]));
        }
        __syncthreads();

        int ntile = tile + G1_CTAS;
        if (ntile < NT_G1) {
#pragma unroll
            for (int j = 0; j < 4; j++) {
                int slot = tid + j * 512;
                int r = slot >> 4, cc = slot & 15;
                int gr = ntile * 128 + r;
                float4 a = make_float4(0.f, 0.f, 0.f, 0.f), b = a;
                if (gr < NN) {
                    const float4* xp = reinterpret_cast<const float4*>(X + (size_t)gr * F + cc * 8);
                    a = xp[0]; b = xp[1];
                }
                pf[2 * j] = a; pf[2 * j + 1] = b;
            }
        }

        int rowBase = tile * 128;
#pragma unroll
        for (int half = 0; half < 2; half++) {
            float acc[2][4][4];
#pragma unroll
            for (int mt = 0; mt < 2; mt++)
#pragma unroll
                for (int nt = 0; nt < 4; nt++)
#pragma unroll
                    for (int e = 0; e < 4; e++) acc[mt][nt][e] = 0.f;

#pragma unroll
            for (int ks = 0; ks < 8; ks++) {
                uint32_t kb = ks * 32;
                uint32_t ahi[2][4], alo[2][4], bhi[4][2], blo[4][2];
#pragma unroll
                for (int mt = 0; mt < 2; mt++) {
                    uint32_t ro = (a_row + mt * 16) * (RS * 2) + kb + a_coff;
                    ldm_x4(ahi[mt], sb + OFF_AHI + ro);
                    ldm_x4(alo[mt], sb + OFF_ALO + ro);
                }
#pragma unroll
                for (int nt = 0; nt < 4; nt++) {
                    uint32_t br = wnBase + half * 32 + nt * 8 + b_rowL;
                    uint32_t ro = br * (RS * 2) + kb + b_coff;
                    ldm_x2(bhi[nt], sb + OFF_BHI + ro);
                    ldm_x2(blo[nt], sb + OFF_BLO + ro);
                }
#pragma unroll
                for (int mt = 0; mt < 2; mt++)
#pragma unroll
                    for (int nt = 0; nt < 4; nt++) {
                        mma16816(acc[mt][nt], ahi[mt], bhi[nt]);
                        mma16816(acc[mt][nt], alo[mt], bhi[nt]);
                        mma16816(acc[mt][nt], ahi[mt], blo[nt]);
                    }
            }

#pragma unroll
            for (int mt = 0; mt < 2; mt++) {
                int r0 = rowBase + wm + mt * 16 + (lane >> 2);
                int r1 = r0 + 8;
#pragma unroll
                for (int nt = 0; nt < 4; nt++) {
                    int c = wnBase + half * 32 + nt * 8 + (lane & 3) * 2;
                    if (c < 128) {
                        float bs0 = __ldg(&b1[c]), bs1 = __ldg(&b1[c + 1]);
                        if (r0 < NN)
                            *reinterpret_cast<float2*>(g_h1 + (size_t)r0 * F + c) =
                                make_float2(acc[mt][nt][0] + bs0, acc[mt][nt][1] + bs1);
                        if (r1 < NN)
                            *reinterpret_cast<float2*>(g_h1 + (size_t)r1 * F + c) =
                                make_float2(acc[mt][nt][2] + bs0, acc[mt][nt][3] + bs1);
                    } else {
                        int cc = c - 128;
                        if (r0 < NN)
                            *reinterpret_cast<uint32_t*>(g_nbh + (size_t)r0 * F + cc) =
                                pack_bf2(acc[mt][nt][0], acc[mt][nt][1]);
                        if (r1 < NN)
                            *reinterpret_cast<uint32_t*>(g_nbh + (size_t)r1 * F + cc) =
                                pack_bf2(acc[mt][nt][2], acc[mt][nt][3]);
                    }
                }
            }
        }
        __syncthreads();
    }
}

// ------- layer-1 aggregate: 16 lanes/node, uint4 gather ---------------------
__global__ void agg1_k() {
    int warp = (blockIdx.x * blockDim.x + threadIdx.x) >> 5;
    int lane = threadIdx.x & 31;
    int node = warp * 2 + (lane >> 4);
    if (node >= NN) return;
    int sl = lane & 15;
    int beg = g_rowoff[node], end = g_rowoff[node + 1];
    float s[8] = {0.f, 0.f, 0.f, 0.f, 0.f, 0.f, 0.f, 0.f};
    int e = beg;
    for (; e + 4 <= end; e += 4) {
        int idx[4];
        uint4 u[4];
#pragma unroll
        for (int j = 0; j < 4; j++) idx[j] = g_esrc[e + j];
#pragma unroll
        for (int j = 0; j < 4; j++)
            u[j] = reinterpret_cast<const uint4*>(g_nbh + (size_t)idx[j] * F)[sl];
#pragma unroll
        for (int j = 0; j < 4; j++) {
            float2 a0 = __bfloat1622float2(*reinterpret_cast<__nv_bfloat162*>(&u[j].x));
            float2 a1 = __bfloat1622float2(*reinterpret_cast<__nv_bfloat162*>(&u[j].y));
            float2 a2 = __bfloat1622float2(*reinterpret_cast<__nv_bfloat162*>(&u[j].z));
            float2 a3 = __bfloat1622float2(*reinterpret_cast<__nv_bfloat162*>(&u[j].w));
            s[0] += a0.x; s[1] += a0.y; s[2] += a1.x; s[3] += a1.y;
            s[4] += a2.x; s[5] += a2.y; s[6] += a3.x; s[7] += a3.y;
        }
    }
    for (; e < end; e++) {
        uint4 u = reinterpret_cast<const uint4*>(g_nbh + (size_t)g_esrc[e] * F)[sl];
        float2 a0 = __bfloat1622float2(*reinterpret_cast<__nv_bfloat162*>(&u.x));
        float2 a1 = __bfloat1622float2(*reinterpret_cast<__nv_bfloat162*>(&u.y));
        float2 a2 = __bfloat1622float2(*reinterpret_cast<__nv_bfloat162*>(&u.z));
        float2 a3 = __bfloat1622float2(*reinterpret_cast<__nv_bfloat162*>(&u.w));
        s[0] += a0.x; s[1] += a0.y; s[2] += a1.x; s[3] += a1.y;
        s[4] += a2.x; s[5] += a2.y; s[6] += a3.x; s[7] += a3.y;
    }
    float inv = 1.0f / fmaxf((float)(end - beg), 1.0f);
    const float4* hp = reinterpret_cast<const float4*>(g_h1 + (size_t)node * F) + sl * 2;
    float4 h0 = hp[0], h1v = hp[1];
    float r[8];
    r[0] = fmaxf(h0.x + s[0] * inv, 0.f);
    r[1] = fmaxf(h0.y + s[1] * inv, 0.f);
    r[2] = fmaxf(h0.z + s[2] * inv, 0.f);
    r[3] = fmaxf(h0.w + s[3] * inv, 0.f);
    r[4] = fmaxf(h1v.x + s[4] * inv, 0.f);
    r[5] = fmaxf(h1v.y + s[5] * inv, 0.f);
    r[6] = fmaxf(h1v.z + s[6] * inv, 0.f);
    r[7] = fmaxf(h1v.w + s[7] * inv, 0.f);
    float hi[8], lo[8];
#pragma unroll
    for (int j = 0; j < 8; j++) {
        hi[j] = __bfloat162float(__float2bfloat16(r[j]));
        lo[j] = r[j] - hi[j];
    }
    uint4 uh = make_uint4(pack_bf2(hi[0], hi[1]), pack_bf2(hi[2], hi[3]),
                          pack_bf2(hi[4], hi[5]), pack_bf2(hi[6], hi[7]));
    uint4 ul = make_uint4(pack_bf2(lo[0], lo[1]), pack_bf2(lo[2], lo[3]),
                          pack_bf2(lo[4], lo[5]), pack_bf2(lo[6], lo[7]));
    reinterpret_cast<uint4*>(g_h1hi + (size_t)node * F)[sl] = uh;
    reinterpret_cast<uint4*>(g_h1lo + (size_t)node * F)[sl] = ul;
}

// ---------------- layer-2 GEMM (mma.sync, N=32 = [self|neigh]) --------------
#define B2_B (32 * RS * 2)
#define OFF2_AHI 0
#define OFF2_ALO (TILE_B)
#define OFF2_BHI (2 * TILE_B)
#define OFF2_BLO (2 * TILE_B + B2_B)
#define SMEM_G2 (2 * TILE_B + 2 * B2_B)

__global__ void __launch_bounds__(256, 1)
gemm2_mma(const float* __restrict__ b2, float* __restrict__ out) {
    extern __shared__ char smem[];
    uint32_t sb = smem_u32(smem);
    int tid = threadIdx.x, wid = tid >> 5, lane = tid & 31;
    int rowBase = blockIdx.x * 128;

    for (int i = tid; i < 128 * 16; i += 256) {
        int r = i >> 4, cc = i & 15;
        uint32_t so = (uint32_t)r * (RS * 2) + cc * 16;
        int gr = rowBase + r;
        uint4 vh = make_uint4(0, 0, 0, 0), vl = make_uint4(0, 0, 0, 0);
        if (gr < NN) {
            vh = reinterpret_cast<const uint4*>(g_h1hi + (size_t)gr * F)[cc];
            vl = reinterpret_cast<const uint4*>(g_h1lo + (size_t)gr * F)[cc];
        }
        *reinterpret_cast<uint4*>(smem + OFF2_AHI + so) = vh;
        *reinterpret_cast<uint4*>(smem + OFF2_ALO + so) = vl;
    }
    for (int i = tid; i < 32 * 16; i += 256) {
        int r = i >> 4, cc = i & 15;
        uint32_t so = (uint32_t)r * (RS * 2) + cc * 16;
        *reinterpret_cast<uint4*>(smem + OFF2_BHI + so) =
            reinterpret_cast<const uint4*>(g_w2Thi + (size_t)r * F)[cc];
        *reinterpret_cast<uint4*>(smem + OFF2_BLO + so) =
            reinterpret_cast<const uint4*>(g_w2Tlo + (size_t)r * F)[cc];
    }
    __syncthreads();

    int wm = (wid & 3) * 32, wn = (wid >> 2) * 16;
    float acc[2][2][4];
#pragma unroll
    for (int mt = 0; mt < 2; mt++)
#pragma unroll
        for (int nt = 0; nt < 2; nt++)
#pragma unroll
            for (int e = 0; e < 4; e++) acc[mt][nt][e] = 0.f;

    uint32_t a_row = wm + (lane & 15);
    uint32_t a_coff = (lane >> 4) * 16;
    uint32_t b_row = wn + (lane & 7);
    uint32_t b_coff = ((lane >> 3) & 1) * 16;

#pragma unroll
    for (int ks = 0; ks < 8; ks++) {
        uint32_t kb = ks * 32;
        uint32_t ahi[2][4], alo[2][4], bhi[2][2], blo[2][2];
#pragma unroll
        for (int mt = 0; mt < 2; mt++) {
            uint32_t ro = (a_row + mt * 16) * (RS * 2) + kb + a_coff;
            ldm_x4(ahi[mt], sb + OFF2_AHI + ro);
            ldm_x4(alo[mt], sb + OFF2_ALO + ro);
        }
#pragma unroll
        for (int nt = 0; nt < 2; nt++) {
            uint32_t ro = (b_row + nt * 8) * (RS * 2) + kb + b_coff;
            ldm_x2(bhi[nt], sb + OFF2_BHI + ro);
            ldm_x2(blo[nt], sb + OFF2_BLO + ro);
        }
#pragma unroll
        for (int mt = 0; mt < 2; mt++)
#pragma unroll
            for (int nt = 0; nt < 2; nt++) {
                mma16816(acc[mt][nt], ahi[mt], bhi[nt]);
                mma16816(acc[mt][nt], alo[mt], bhi[nt]);
                mma16816(acc[mt][nt], ahi[mt], blo[nt]);
            }
    }

#pragma unroll
    for (int mt = 0; mt < 2; mt++) {
        int r0 = rowBase + wm + mt * 16 + (lane >> 2);
        int r1 = r0 + 8;
#pragma unroll
        for (int nt = 0; nt < 2; nt++) {
            int cg = wn + nt * 8 + (lane & 3) * 2;
            if (cg < 16) {
                float bs0 = __ldg(&b2[cg]), bs1 = __ldg(&b2[cg + 1]);
                if (r0 < NN)
                    *reinterpret_cast<float2*>(out + (size_t)r0 * NC + cg) =
                        make_float2(acc[mt][nt][0] + bs0, acc[mt][nt][1] + bs1);
                if (r1 < NN)
                    *reinterpret_cast<float2*>(out + (size_t)r1 * NC + cg) =
                        make_float2(acc[mt][nt][2] + bs0, acc[mt][nt][3] + bs1);
            } else {
                int cd = cg - 16;
                if (r0 < NN)
                    *reinterpret_cast<float2*>(g_D + (size_t)r0 * NC + cd) =
                        make_float2(acc[mt][nt][0], acc[mt][nt][1]);
                if (r1 < NN)
                    *reinterpret_cast<float2*>(g_D + (size_t)r1 * NC + cd) =
                        make_float2(acc[mt][nt][2], acc[mt][nt][3]);
            }
        }
    }
}

// ---------------- layer-2 aggregate + add: 8 threads/node, float2 -----------
__global__ void agg2_k(float* __restrict__ out) {
    int idx = blockIdx.x * blockDim.x + threadIdx.x;
    int node = idx >> 3;
    if (node >= NN) return;
    int dim2 = idx & 7;                      // float2 slot: dims [2*dim2, 2*dim2+1]
    int beg = g_rowoff[node], end = g_rowoff[node + 1];
    float sx = 0.f, sy = 0.f;
    int e = beg;
    for (; e + 8 <= end; e += 8) {
        int id[8];
        float2 v[8];
#pragma unroll
        for (int j = 0; j < 8; j++) id[j] = g_esrc[e + j];
#pragma unroll
        for (int j = 0; j < 8; j++)
            v[j] = reinterpret_cast<const float2*>(g_D + (size_t)id[j] * NC)[dim2];
#pragma unroll
        for (int j = 0; j < 8; j++) { sx += v[j].x; sy += v[j].y; }
    }
    for (; e + 4 <= end; e += 4) {
        int id[4];
        float2 v[4];
#pragma unroll
        for (int j = 0; j < 4; j++) id[j] = g_esrc[e + j];
#pragma unroll
        for (int j = 0; j < 4; j++)
            v[j] = reinterpret_cast<const float2*>(g_D + (size_t)id[j] * NC)[dim2];
#pragma unroll
        for (int j = 0; j < 4; j++) { sx += v[j].x; sy += v[j].y; }
    }
    for (; e < end; e++) {
        float2 v = reinterpret_cast<const float2*>(g_D + (size_t)g_esrc[e] * NC)[dim2];
        sx += v.x; sy += v.y;
    }
    float inv = 1.0f / fmaxf((float)(end - beg), 1.0f);
    float2* op = reinterpret_cast<float2*>(out + (size_t)node * NC) + dim2;
    float2 o = *op;
    o.x += sx * inv;
    o.y += sy * inv;
    *op = o;
}

// ---------------- launch (R14 schedule) -------------------------------------
extern "C" void kernel_launch(void* const* d_in, const int* in_sizes, int n_in,
                              void* d_out, int out_size)
{
    const float* in_feat = (const float*)d_in[0];
    const void*  src     = d_in[1];
    const void*  dst     = d_in[2];
    const float* Wself1  = (const float*)d_in[3];
    const float* Wneigh1 = (const float*)d_in[4];
    const float* b1      = (const float*)d_in[5];
    const float* Wself2  = (const float*)d_in[6];
    const float* Wneigh2 = (const float*)d_in[7];
    const float* b2      = (const float*)d_in[8];
    float* out = (float*)d_out;

    static cudaStream_t s2 = nullptr;
    static cudaEvent_t evFork = nullptr, evJoin = nullptr;
    if (!s2) {
        cudaFuncSetAttribute(gemm1_mma, cudaFuncAttributeMaxDynamicSharedMemorySize, SMEM_G1);
        cudaFuncSetAttribute(gemm2_mma, cudaFuncAttributeMaxDynamicSharedMemorySize, SMEM_G2);
        cudaStreamCreateWithFlags(&s2, cudaStreamNonBlocking);
        cudaEventCreateWithFlags(&evFork, cudaEventDisableTiming);
        cudaEventCreateWithFlags(&evJoin, cudaEventDisableTiming);
    }

    // prep on main stream (zero + detect + weight conversion)
    prep_k<<<NBLK, 256>>>((const int*)dst, Wself1, Wneigh1, Wself2, Wneigh2);

    // fork: CSR chain on s2, gemm1 on main
    cudaEventRecord(evFork, 0);
    cudaStreamWaitEvent(s2, evFork, 0);

    count_k<<<(NE + 255) / 256, 256, 0, s2>>>(dst);
    scanA_k<<<NBLK, 256, 0, s2>>>();
    scanC_k<<<NBLK, 256, 0, s2>>>();
    fill_k <<<(NE + 255) / 256, 256, 0, s2>>>(src, dst);
    cudaEventRecord(evJoin, s2);

    gemm1_mma<<<G1_CTAS, 512, SMEM_G1>>>(in_feat, b1);

    // join: agg1 needs both fill_k (s2) and gemm1 (main)
    cudaStreamWaitEvent(0, evJoin, 0);

    agg1_k<<<(NN / 2 * 32 + 255) / 256, 256>>>();
    gemm2_mma<<<(NN + 127) / 128, 256, SMEM_G2>>>(b2, out);
    agg2_k<<<(NN * 8 + 255) / 256, 256>>>(out);
}